// round 8
// baseline (speedup 1.0000x reference)
#include <cuda_runtime.h>
#include <math.h>

#define HKD  128
#define NKH  16
#define NVH  32
#define QKVD 8192

__device__ __forceinline__ float wredu(float v) {
#pragma unroll
    for (int o = 16; o; o >>= 1) v += __shfl_xor_sync(0xffffffffu, v, o);
    return v;
}

__device__ __forceinline__ float dot4(float4 a, float4 b) {
    return a.x * b.x + a.y * b.y + a.z * b.z + a.w * b.w;
}

__global__ __launch_bounds__(128) void gdn_decode_kernel(
    const float* __restrict__ mixed_qkv,
    const float* __restrict__ bgate,
    const float* __restrict__ agate,
    const float* __restrict__ conv_state,
    const float* __restrict__ conv_w,
    const float* __restrict__ ssm,
    const float* __restrict__ alog,
    const float* __restrict__ dt_bias,
    float* __restrict__ out)
{
    const int bh = blockIdx.x;
    const int b  = bh >> 5;
    const int h  = bh & 31;
    const int hq = h >> 1;                 // GROUP = 2
    const int t    = threadIdx.x;
    const int lane = t & 31;
    const int wid  = t >> 5;

    __shared__ __align__(16) float q_s[HKD];
    __shared__ __align__(16) float k_s[HKD];
    __shared__ __align__(16) float v_s[HKD];
    __shared__ float red[12];

    // ---- prefetch batch 0 of state rows BEFORE any prologue work ----
    const float4* Sb = (const float4*)(ssm + (size_t)bh * HKD * HKD)
                       + (size_t)wid * 32 * 32 + lane;
    float4 c0 = __ldcs(Sb + 0 * 32);
    float4 c1 = __ldcs(Sb + 1 * 32);
    float4 c2 = __ldcs(Sb + 2 * 32);
    float4 c3 = __ldcs(Sb + 3 * 32);

    // ---- causal conv (4 taps) + SiLU for this CTA's q/k/v channels ----
    const float* cs = conv_state + (size_t)b * 3 * QKVD;
    const float* mq = mixed_qkv  + (size_t)b * QKVD;
    const int cq = hq * HKD + t;
    const int ck = NKH * HKD + hq * HKD + t;
    const int cv = 2 * NKH * HKD + h * HKD + t;

    float qx, kx, vx;
    {
        float4 w = *(const float4*)(conv_w + (size_t)cq * 4);
        float x  = cs[cq] * w.x + cs[QKVD + cq] * w.y + cs[2 * QKVD + cq] * w.z + mq[cq] * w.w;
        qx = x / (1.f + expf(-x));

        w = *(const float4*)(conv_w + (size_t)ck * 4);
        x = cs[ck] * w.x + cs[QKVD + ck] * w.y + cs[2 * QKVD + ck] * w.z + mq[ck] * w.w;
        kx = x / (1.f + expf(-x));

        w = *(const float4*)(conv_w + (size_t)cv * 4);
        x = cs[cv] * w.x + cs[QKVD + cv] * w.y + cs[2 * QKVD + cv] * w.z + mq[cv] * w.w;
        vx = x / (1.f + expf(-x));
    }

    // raw values to shared, single fused reduction (q^2, k^2, q.k)
    q_s[t] = qx;
    k_s[t] = kx;
    v_s[t] = vx;
    float pq = wredu(qx * qx);
    float pk = wredu(kx * kx);
    float pc = wredu(qx * kx);
    if (lane == 0) { red[wid] = pq; red[4 + wid] = pk; red[8 + wid] = pc; }

    // ---- gating scalars (independent of the reduction; hides sync) ----
    const float aa   = agate[(size_t)b * NVH + h] + dt_bias[h];
    const float sp   = fmaxf(aa, 0.f) + log1pf(expf(-fabsf(aa)));   // softplus
    const float eg   = expf(-expf(alog[h]) * sp);                   // exp(g)
    const float beta = 1.f / (1.f + expf(-bgate[(size_t)b * NVH + h]));

    __syncthreads();   // the only barrier

    const float rq = rsqrtf(red[0] + red[1] + red[2] + red[3] + 1e-6f)
                     * 0.08838834764831845f;                        // * HK^-0.5
    const float rk = rsqrtf(red[4] + red[5] + red[6] + red[7] + 1e-6f);
    const float kq = (red[8] + red[9] + red[10] + red[11]) * rq * rk;

    float4 q4 = ((const float4*)q_s)[lane];
    q4.x *= rq; q4.y *= rq; q4.z *= rq; q4.w *= rq;
    float4 k4 = ((const float4*)k_s)[lane];
    k4.x *= rk; k4.y *= rk; k4.z *= rk; k4.w *= rk;

    // epilogue constants: o = eg*dq + bk*v - bke*dk
    const float bk  = beta * kq;
    const float bke = bk * eg;

    float*       op = out + (size_t)bh * HKD + wid * 32;
    const float* vr = v_s + wid * 32;

    // ---- 7 batches with distance-1 prefetch + peeled final batch ----
#pragma unroll
    for (int j = 0; j < 7; j++) {
        float4 n0 = __ldcs(Sb + ((j + 1) * 4 + 0) * 32);
        float4 n1 = __ldcs(Sb + ((j + 1) * 4 + 1) * 32);
        float4 n2 = __ldcs(Sb + ((j + 1) * 4 + 2) * 32);
        float4 n3 = __ldcs(Sb + ((j + 1) * 4 + 3) * 32);

        float dk0 = dot4(c0, k4), dq0 = dot4(c0, q4);
        float dk1 = dot4(c1, k4), dq1 = dot4(c1, q4);
        float dk2 = dot4(c2, k4), dq2 = dot4(c2, q4);
        float dk3 = dot4(c3, k4), dq3 = dot4(c3, q4);

        dk0 = wredu(dk0); dq0 = wredu(dq0);
        dk1 = wredu(dk1); dq1 = wredu(dq1);
        dk2 = wredu(dk2); dq2 = wredu(dq2);
        dk3 = wredu(dk3); dq3 = wredu(dq3);

        if (lane == 0) {
            const int r = j * 4;
            __stcs(&op[r + 0], fmaf(eg, dq0, fmaf(bk, vr[r + 0], -bke * dk0)));
            __stcs(&op[r + 1], fmaf(eg, dq1, fmaf(bk, vr[r + 1], -bke * dk1)));
            __stcs(&op[r + 2], fmaf(eg, dq2, fmaf(bk, vr[r + 2], -bke * dk2)));
            __stcs(&op[r + 3], fmaf(eg, dq3, fmaf(bk, vr[r + 3], -bke * dk3)));
        }

        c0 = n0; c1 = n1; c2 = n2; c3 = n3;
    }

    // final batch (no prefetch, no dead-buffer init)
    {
        float dk0 = dot4(c0, k4), dq0 = dot4(c0, q4);
        float dk1 = dot4(c1, k4), dq1 = dot4(c1, q4);
        float dk2 = dot4(c2, k4), dq2 = dot4(c2, q4);
        float dk3 = dot4(c3, k4), dq3 = dot4(c3, q4);

        dk0 = wredu(dk0); dq0 = wredu(dq0);
        dk1 = wredu(dk1); dq1 = wredu(dq1);
        dk2 = wredu(dk2); dq2 = wredu(dq2);
        dk3 = wredu(dk3); dq3 = wredu(dq3);

        if (lane == 0) {
            __stcs(&op[28], fmaf(eg, dq0, fmaf(bk, vr[28], -bke * dk0)));
            __stcs(&op[29], fmaf(eg, dq1, fmaf(bk, vr[29], -bke * dk1)));
            __stcs(&op[30], fmaf(eg, dq2, fmaf(bk, vr[30], -bke * dk2)));
            __stcs(&op[31], fmaf(eg, dq3, fmaf(bk, vr[31], -bke * dk3)));
        }
    }
}

extern "C" void kernel_launch(void* const* d_in, const int* in_sizes, int n_in,
                              void* d_out, int out_size)
{
    const float* mixed_qkv  = (const float*)d_in[0];
    const float* bgate      = (const float*)d_in[1];
    const float* agate      = (const float*)d_in[2];
    const float* conv_state = (const float*)d_in[3];
    const float* conv_w     = (const float*)d_in[4];
    const float* ssm        = (const float*)d_in[5];
    const float* alog       = (const float*)d_in[6];
    const float* dt_bias    = (const float*)d_in[7];
    float* out = (float*)d_out;

    const int B = in_sizes[0] / QKVD;
    gdn_decode_kernel<<<B * NVH, 128>>>(mixed_qkv, bgate, agate, conv_state,
                                        conv_w, ssm, alog, dt_bias, out);
}

// round 9
// speedup vs baseline: 1.0721x; 1.0721x over previous
#include <cuda_runtime.h>
#include <math.h>

#define HKD  128
#define NKH  16
#define NVH  32
#define QKVD 8192

__device__ __forceinline__ float wredu(float v) {
#pragma unroll
    for (int o = 16; o; o >>= 1) v += __shfl_xor_sync(0xffffffffu, v, o);
    return v;
}

__device__ __forceinline__ float dot4(float4 a, float4 b) {
    return a.x * b.x + a.y * b.y + a.z * b.z + a.w * b.w;
}

__global__ __launch_bounds__(128) void gdn_decode_kernel(
    const float* __restrict__ mixed_qkv,
    const float* __restrict__ bgate,
    const float* __restrict__ agate,
    const float* __restrict__ conv_state,
    const float* __restrict__ conv_w,
    const float* __restrict__ ssm,
    const float* __restrict__ alog,
    const float* __restrict__ dt_bias,
    float* __restrict__ out)
{
    const int bh = blockIdx.x;
    const int b  = bh >> 5;
    const int h  = bh & 31;
    const int hq = h >> 1;                 // GROUP = 2
    const int t    = threadIdx.x;
    const int lane = t & 31;
    const int wid  = t >> 5;

    __shared__ __align__(16) float q_s[HKD];
    __shared__ __align__(16) float k_s[HKD];
    __shared__ __align__(16) float v_s[HKD];
    __shared__ float red[12];

    // ---- prefetch batch 0 of state rows BEFORE any prologue work ----
    const float4* Sb = (const float4*)(ssm + (size_t)bh * HKD * HKD)
                       + (size_t)wid * 32 * 32 + lane;
    float4 c0 = __ldcs(Sb + 0 * 32);
    float4 c1 = __ldcs(Sb + 1 * 32);
    float4 c2 = __ldcs(Sb + 2 * 32);
    float4 c3 = __ldcs(Sb + 3 * 32);

    // ---- causal conv (4 taps) + SiLU for this CTA's q/k/v channels ----
    const float* cs = conv_state + (size_t)b * 3 * QKVD;
    const float* mq = mixed_qkv  + (size_t)b * QKVD;
    const int cq = hq * HKD + t;
    const int ck = NKH * HKD + hq * HKD + t;
    const int cv = 2 * NKH * HKD + h * HKD + t;

    float qx, kx, vx;
    {
        float4 w = *(const float4*)(conv_w + (size_t)cq * 4);
        float x  = cs[cq] * w.x + cs[QKVD + cq] * w.y + cs[2 * QKVD + cq] * w.z + mq[cq] * w.w;
        qx = x / (1.f + expf(-x));

        w = *(const float4*)(conv_w + (size_t)ck * 4);
        x = cs[ck] * w.x + cs[QKVD + ck] * w.y + cs[2 * QKVD + ck] * w.z + mq[ck] * w.w;
        kx = x / (1.f + expf(-x));

        w = *(const float4*)(conv_w + (size_t)cv * 4);
        x = cs[cv] * w.x + cs[QKVD + cv] * w.y + cs[2 * QKVD + cv] * w.z + mq[cv] * w.w;
        vx = x / (1.f + expf(-x));
    }

    // raw values to shared, single fused reduction (q^2, k^2, q.k)
    q_s[t] = qx;
    k_s[t] = kx;
    v_s[t] = vx;
    float pq = wredu(qx * qx);
    float pk = wredu(kx * kx);
    float pc = wredu(qx * kx);
    if (lane == 0) { red[wid] = pq; red[4 + wid] = pk; red[8 + wid] = pc; }

    // ---- gating scalars (independent of the reduction; hides sync) ----
    const float aa   = agate[(size_t)b * NVH + h] + dt_bias[h];
    const float sp   = fmaxf(aa, 0.f) + log1pf(expf(-fabsf(aa)));   // softplus
    const float eg   = expf(-expf(alog[h]) * sp);                   // exp(g)
    const float beta = 1.f / (1.f + expf(-bgate[(size_t)b * NVH + h]));

    __syncthreads();   // the only barrier

    const float rq = rsqrtf(red[0] + red[1] + red[2] + red[3] + 1e-6f)
                     * 0.08838834764831845f;                        // * HK^-0.5
    const float rk = rsqrtf(red[4] + red[5] + red[6] + red[7] + 1e-6f);
    const float kq = (red[8] + red[9] + red[10] + red[11]) * rq * rk;

    float4 q4 = ((const float4*)q_s)[lane];
    q4.x *= rq; q4.y *= rq; q4.z *= rq; q4.w *= rq;
    float4 k4 = ((const float4*)k_s)[lane];
    k4.x *= rk; k4.y *= rk; k4.z *= rk; k4.w *= rk;

    float*       op = out + (size_t)bh * HKD + wid * 32;
    const float* vr = v_s + wid * 32;

    // ---- 8 batches of 4 rows, double-buffered: next loads issue before
    //      the current batch's shuffle-reduction chains ----
#pragma unroll
    for (int j = 0; j < 8; j++) {
        float4 n0 = {}, n1 = {}, n2 = {}, n3 = {};
        if (j < 7) {
            n0 = __ldcs(Sb + ((j + 1) * 4 + 0) * 32);
            n1 = __ldcs(Sb + ((j + 1) * 4 + 1) * 32);
            n2 = __ldcs(Sb + ((j + 1) * 4 + 2) * 32);
            n3 = __ldcs(Sb + ((j + 1) * 4 + 3) * 32);
        }

        float dk0 = dot4(c0, k4), dq0 = dot4(c0, q4);
        float dk1 = dot4(c1, k4), dq1 = dot4(c1, q4);
        float dk2 = dot4(c2, k4), dq2 = dot4(c2, q4);
        float dk3 = dot4(c3, k4), dq3 = dot4(c3, q4);

        dk0 = wredu(dk0); dq0 = wredu(dq0);
        dk1 = wredu(dk1); dq1 = wredu(dq1);
        dk2 = wredu(dk2); dq2 = wredu(dq2);
        dk3 = wredu(dk3); dq3 = wredu(dq3);

        if (lane == 0) {
            const int r = j * 4;
            op[r + 0] = eg * dq0 + beta * (vr[r + 0] - eg * dk0) * kq;
            op[r + 1] = eg * dq1 + beta * (vr[r + 1] - eg * dk1) * kq;
            op[r + 2] = eg * dq2 + beta * (vr[r + 2] - eg * dk2) * kq;
            op[r + 3] = eg * dq3 + beta * (vr[r + 3] - eg * dk3) * kq;
        }

        c0 = n0; c1 = n1; c2 = n2; c3 = n3;
    }
}

extern "C" void kernel_launch(void* const* d_in, const int* in_sizes, int n_in,
                              void* d_out, int out_size)
{
    const float* mixed_qkv  = (const float*)d_in[0];
    const float* bgate      = (const float*)d_in[1];
    const float* agate      = (const float*)d_in[2];
    const float* conv_state = (const float*)d_in[3];
    const float* conv_w     = (const float*)d_in[4];
    const float* ssm        = (const float*)d_in[5];
    const float* alog       = (const float*)d_in[6];
    const float* dt_bias    = (const float*)d_in[7];
    float* out = (float*)d_out;

    const int B = in_sizes[0] / QKVD;
    gdn_decode_kernel<<<B * NVH, 128>>>(mixed_qkv, bgate, agate, conv_state,
                                        conv_w, ssm, alog, dt_bias, out);
}

// round 11
// speedup vs baseline: 1.0768x; 1.0044x over previous
#include <cuda_runtime.h>
#include <math.h>

#define HKD  128
#define NKH  16
#define NVH  32
#define QKVD 8192

__device__ __forceinline__ float wredu(float v) {
#pragma unroll
    for (int o = 16; o; o >>= 1) v += __shfl_xor_sync(0xffffffffu, v, o);
    return v;
}

__device__ __forceinline__ float dot4(float4 a, float4 b) {
    return a.x * b.x + a.y * b.y + a.z * b.z + a.w * b.w;
}

__global__ __launch_bounds__(128) void gdn_decode_kernel(
    const float* __restrict__ mixed_qkv,
    const float* __restrict__ bgate,
    const float* __restrict__ agate,
    const float* __restrict__ conv_state,
    const float* __restrict__ conv_w,
    const float* __restrict__ ssm,
    const float* __restrict__ alog,
    const float* __restrict__ dt_bias,
    float* __restrict__ out)
{
    const int bh = blockIdx.x;
    const int b  = bh >> 5;
    const int h  = bh & 31;
    const int hq = h >> 1;                 // GROUP = 2
    const int t    = threadIdx.x;
    const int lane = t & 31;
    const int wid  = t >> 5;

    __shared__ __align__(16) float q_s[HKD];
    __shared__ __align__(16) float k_s[HKD];
    __shared__ __align__(16) float v_s[HKD];
    __shared__ float red[12];

    // ---- prefetch batch 0 of state rows BEFORE any prologue work ----
    const float4* Sb = (const float4*)(ssm + (size_t)bh * HKD * HKD)
                       + (size_t)wid * 32 * 32 + lane;
    float4 c0 = __ldcs(Sb + 0 * 32);
    float4 c1 = __ldcs(Sb + 1 * 32);
    float4 c2 = __ldcs(Sb + 2 * 32);
    float4 c3 = __ldcs(Sb + 3 * 32);

    // ---- causal conv (4 taps) + SiLU for this CTA's q/k/v channels ----
    const float* cs = conv_state + (size_t)b * 3 * QKVD;
    const float* mq = mixed_qkv  + (size_t)b * QKVD;
    const int cq = hq * HKD + t;
    const int ck = NKH * HKD + hq * HKD + t;
    const int cv = 2 * NKH * HKD + h * HKD + t;

    float qx, kx, vx;
    {
        float4 w = *(const float4*)(conv_w + (size_t)cq * 4);
        float x  = cs[cq] * w.x + cs[QKVD + cq] * w.y + cs[2 * QKVD + cq] * w.z + mq[cq] * w.w;
        qx = x / (1.f + expf(-x));

        w = *(const float4*)(conv_w + (size_t)ck * 4);
        x = cs[ck] * w.x + cs[QKVD + ck] * w.y + cs[2 * QKVD + ck] * w.z + mq[ck] * w.w;
        kx = x / (1.f + expf(-x));

        w = *(const float4*)(conv_w + (size_t)cv * 4);
        x = cs[cv] * w.x + cs[QKVD + cv] * w.y + cs[2 * QKVD + cv] * w.z + mq[cv] * w.w;
        vx = x / (1.f + expf(-x));
    }

    // raw values to shared, single fused reduction (q^2, k^2, q.k)
    q_s[t] = qx;
    k_s[t] = kx;
    v_s[t] = vx;
    float pq = wredu(qx * qx);
    float pk = wredu(kx * kx);
    float pc = wredu(qx * kx);
    if (lane == 0) { red[wid] = pq; red[4 + wid] = pk; red[8 + wid] = pc; }

    // ---- gating scalars (independent of the reduction; hides sync) ----
    const float aa   = agate[(size_t)b * NVH + h] + dt_bias[h];
    const float sp   = fmaxf(aa, 0.f) + log1pf(expf(-fabsf(aa)));   // softplus
    const float eg   = expf(-expf(alog[h]) * sp);                   // exp(g)
    const float beta = 1.f / (1.f + expf(-bgate[(size_t)b * NVH + h]));

    __syncthreads();   // the only barrier

    const float rq = rsqrtf(red[0] + red[1] + red[2] + red[3] + 1e-6f)
                     * 0.08838834764831845f;                        // * HK^-0.5
    const float rk = rsqrtf(red[4] + red[5] + red[6] + red[7] + 1e-6f);
    const float kq = (red[8] + red[9] + red[10] + red[11]) * rq * rk;

    float4 q4 = ((const float4*)q_s)[lane];
    q4.x *= rq; q4.y *= rq; q4.z *= rq; q4.w *= rq;
    float4 k4 = ((const float4*)k_s)[lane];
    k4.x *= rk; k4.y *= rk; k4.z *= rk; k4.w *= rk;

    float*       op = out + (size_t)bh * HKD + wid * 32;
    const float* vr = v_s + wid * 32;

    // ---- 8 batches of 4 rows, double-buffered: next loads issue before
    //      the current batch's shuffle-reduction chains ----
#pragma unroll
    for (int j = 0; j < 8; j++) {
        float4 n0 = {}, n1 = {}, n2 = {}, n3 = {};
        if (j < 7) {
            n0 = __ldcs(Sb + ((j + 1) * 4 + 0) * 32);
            n1 = __ldcs(Sb + ((j + 1) * 4 + 1) * 32);
            n2 = __ldcs(Sb + ((j + 1) * 4 + 2) * 32);
            n3 = __ldcs(Sb + ((j + 1) * 4 + 3) * 32);
        }

        float dk0 = dot4(c0, k4), dq0 = dot4(c0, q4);
        float dk1 = dot4(c1, k4), dq1 = dot4(c1, q4);
        float dk2 = dot4(c2, k4), dq2 = dot4(c2, q4);
        float dk3 = dot4(c3, k4), dq3 = dot4(c3, q4);

        dk0 = wredu(dk0); dq0 = wredu(dq0);
        dk1 = wredu(dk1); dq1 = wredu(dq1);
        dk2 = wredu(dk2); dq2 = wredu(dq2);
        dk3 = wredu(dk3); dq3 = wredu(dq3);

        if (lane == 0) {
            const int r = j * 4;
            op[r + 0] = eg * dq0 + beta * (vr[r + 0] - eg * dk0) * kq;
            op[r + 1] = eg * dq1 + beta * (vr[r + 1] - eg * dk1) * kq;
            op[r + 2] = eg * dq2 + beta * (vr[r + 2] - eg * dk2) * kq;
            op[r + 3] = eg * dq3 + beta * (vr[r + 3] - eg * dk3) * kq;
        }

        c0 = n0; c1 = n1; c2 = n2; c3 = n3;
    }
}

extern "C" void kernel_launch(void* const* d_in, const int* in_sizes, int n_in,
                              void* d_out, int out_size)
{
    const float* mixed_qkv  = (const float*)d_in[0];
    const float* bgate      = (const float*)d_in[1];
    const float* agate      = (const float*)d_in[2];
    const float* conv_state = (const float*)d_in[3];
    const float* conv_w     = (const float*)d_in[4];
    const float* ssm        = (const float*)d_in[5];
    const float* alog       = (const float*)d_in[6];
    const float* dt_bias    = (const float*)d_in[7];
    float* out = (float*)d_out;

    const int B = in_sizes[0] / QKVD;
    gdn_decode_kernel<<<B * NVH, 128>>>(mixed_qkv, bgate, agate, conv_state,
                                        conv_w, ssm, alog, dt_bias, out);
}